// round 12
// baseline (speedup 1.0000x reference)
#include <cuda_runtime.h>
#include <cuda_bf16.h>

// NonSparsePLIF: v[t] = where(v[t-1]*d + x[t] >= 1.0, 0, v[t-1]*d + x[t])
// x_seq [T=16, 4194304] f32, decay [1] f32. HBM-bound streaming scan.
// R12: best shape + __ldcs (evict-first read-once loads) + __stwt
// (write-through stores, no L2 allocate). R11 (__stwt alone) = 76.26us,
// DRAM 80.3% — current best. Isolating the load-side hint on top of it.

#define T_STEPS 16
#define SPATIAL 4194304            // 16*64*64*64
#define SPATIAL4 (SPATIAL / 4)     // 1048576 float4 per timestep plane
#define THREADS 256
#define BLOCKS (SPATIAL4 / THREADS)  // 4096, exact
#define VTH 1.0f

__global__ __launch_bounds__(THREADS) void plif_kernel(
    const float4* __restrict__ x,      // [T, SPATIAL4]
    const float* __restrict__ decay,   // [1]
    float4* __restrict__ out)          // [T, SPATIAL4]
{
    const int i = blockIdx.x * THREADS + threadIdx.x;  // always < SPATIAL4

    const float d = decay[0];

    float4 v = make_float4(0.f, 0.f, 0.f, 0.f);

#pragma unroll
    for (int t = 0; t < T_STEPS; ++t) {
        const size_t idx = (size_t)t * SPATIAL4 + i;
        const float4 xt = __ldcs(&x[idx]);   // read-once: evict-first
        v.x = fmaf(v.x, d, xt.x);
        v.y = fmaf(v.y, d, xt.y);
        v.z = fmaf(v.z, d, xt.z);
        v.w = fmaf(v.w, d, xt.w);
        v.x = (v.x >= VTH) ? 0.f : v.x;
        v.y = (v.y >= VTH) ? 0.f : v.y;
        v.z = (v.z >= VTH) ? 0.f : v.z;
        v.w = (v.w >= VTH) ? 0.f : v.w;
        __stwt(&out[idx], v);                // write-through: no L2 allocate
    }
}

extern "C" void kernel_launch(void* const* d_in, const int* in_sizes, int n_in,
                              void* d_out, int out_size)
{
    const float4* x   = (const float4*)d_in[0];
    const float*  dec = (const float*)d_in[1];
    float4*       out = (float4*)d_out;

    plif_kernel<<<BLOCKS, THREADS>>>(x, dec, out);
}

// round 13
// speedup vs baseline: 1.0734x; 1.0734x over previous
#include <cuda_runtime.h>
#include <cuda_bf16.h>

// NonSparsePLIF: v[t] = where(v[t-1]*d + x[t] >= 1.0, 0, v[t-1]*d + x[t])
// x_seq [T=16, 4194304] f32, decay [1] f32.
//
// FINAL — winner of 12 measured variants (R11): 76.26us kernel, DRAM 80.3%
// (6361 GB/s). 1 float4 per thread, block=256, grid=4096 exact cover,
// PLAIN loads (__ldcs collapses ptxas's load scheduling: regs 32->26,
// DRAM -9%), __stwt write-through stores (no L2 write-allocate; best store
// policy by ~1% over __stcs and plain).
//
// Roofline: 512 MB mandatory 1:1 RW traffic, no reuse possible (working set
// 256 MB >> L2, output f32, scan in registers). ~6.36 TB/s is this part's
// achievable mixed-stream HBM ceiling.

#define T_STEPS 16
#define SPATIAL 4194304            // 16*64*64*64
#define SPATIAL4 (SPATIAL / 4)     // 1048576 float4 per timestep plane
#define THREADS 256
#define BLOCKS (SPATIAL4 / THREADS)  // 4096, exact
#define VTH 1.0f

__global__ __launch_bounds__(THREADS) void plif_kernel(
    const float4* __restrict__ x,      // [T, SPATIAL4]
    const float* __restrict__ decay,   // [1]
    float4* __restrict__ out)          // [T, SPATIAL4]
{
    const int i = blockIdx.x * THREADS + threadIdx.x;  // always < SPATIAL4

    const float d = decay[0];

    float4 v = make_float4(0.f, 0.f, 0.f, 0.f);

#pragma unroll
    for (int t = 0; t < T_STEPS; ++t) {
        const size_t idx = (size_t)t * SPATIAL4 + i;
        const float4 xt = x[idx];            // plain load — best measured
        v.x = fmaf(v.x, d, xt.x);
        v.y = fmaf(v.y, d, xt.y);
        v.z = fmaf(v.z, d, xt.z);
        v.w = fmaf(v.w, d, xt.w);
        v.x = (v.x >= VTH) ? 0.f : v.x;
        v.y = (v.y >= VTH) ? 0.f : v.y;
        v.z = (v.z >= VTH) ? 0.f : v.z;
        v.w = (v.w >= VTH) ? 0.f : v.w;
        __stwt(&out[idx], v);                // write-through: no L2 allocate
    }
}

extern "C" void kernel_launch(void* const* d_in, const int* in_sizes, int n_in,
                              void* d_out, int out_size)
{
    const float4* x   = (const float4*)d_in[0];
    const float*  dec = (const float*)d_in[1];
    float4*       out = (float4*)d_out;

    plif_kernel<<<BLOCKS, THREADS>>>(x, dec, out);
}

// round 14
// speedup vs baseline: 1.0821x; 1.0081x over previous
#include <cuda_runtime.h>
#include <cuda_bf16.h>

// NonSparsePLIF: v[t] = where(v[t-1]*d + x[t] >= 1.0, 0, v[t-1]*d + x[t])
// x_seq [T=16, 4194304] f32, decay [1] f32.
//
// FINAL — winner of 13 measured variants (R11, reproduced R13):
// 76.3-76.8us kernel, DRAM ~80% (6.33-6.36 TB/s).
//   - 1 float4 per thread, block=256, grid=4096 (exact cover, no guard)
//   - PLAIN loads (__ldcs collapses ptxas load scheduling: regs 32->26,
//     DRAM 80% -> 71%)
//   - __stwt write-through stores (no L2 write-allocate; best store policy)
//
// Roofline: 512 MB mandatory 1:1 RW traffic, zero reuse possible (touch-once
// input, touch-once f32 output, working set 256 MB >> 126 MB L2, T-scan
// carried in registers). ~6.35 TB/s is the achievable mixed-stream HBM
// ceiling on this part; all non-DRAM pipes <12% utilized. Measured flat or
// worse: __stcs, __ldcs, 2xMLP, persistent grid, block=128, 2-step bursts,
// 256-bit v8 accesses.

#define T_STEPS 16
#define SPATIAL 4194304            // 16*64*64*64
#define SPATIAL4 (SPATIAL / 4)     // 1048576 float4 per timestep plane
#define THREADS 256
#define BLOCKS (SPATIAL4 / THREADS)  // 4096, exact
#define VTH 1.0f

__global__ __launch_bounds__(THREADS) void plif_kernel(
    const float4* __restrict__ x,      // [T, SPATIAL4]
    const float* __restrict__ decay,   // [1]
    float4* __restrict__ out)          // [T, SPATIAL4]
{
    const int i = blockIdx.x * THREADS + threadIdx.x;  // always < SPATIAL4

    const float d = decay[0];

    float4 v = make_float4(0.f, 0.f, 0.f, 0.f);

#pragma unroll
    for (int t = 0; t < T_STEPS; ++t) {
        const size_t idx = (size_t)t * SPATIAL4 + i;
        const float4 xt = x[idx];            // plain load — best measured
        v.x = fmaf(v.x, d, xt.x);
        v.y = fmaf(v.y, d, xt.y);
        v.z = fmaf(v.z, d, xt.z);
        v.w = fmaf(v.w, d, xt.w);
        v.x = (v.x >= VTH) ? 0.f : v.x;
        v.y = (v.y >= VTH) ? 0.f : v.y;
        v.z = (v.z >= VTH) ? 0.f : v.z;
        v.w = (v.w >= VTH) ? 0.f : v.w;
        __stwt(&out[idx], v);                // write-through: no L2 allocate
    }
}

extern "C" void kernel_launch(void* const* d_in, const int* in_sizes, int n_in,
                              void* d_out, int out_size)
{
    const float4* x   = (const float4*)d_in[0];
    const float*  dec = (const float*)d_in[1];
    float4*       out = (float4*)d_out;

    plif_kernel<<<BLOCKS, THREADS>>>(x, dec, out);
}